// round 1
// baseline (speedup 1.0000x reference)
#include <cuda_runtime.h>

// ---------------------------------------------------------------------------
// High_enhancer: sparse avg-pool (stride2, ME semantics) + sparse transposed
// conv (27 offsets, C=32) + residual subtract, all fp32.
//
//   pooled[m]  = sum_{pool pairs} feat[pool_in] / pool_counts[m]
//   out[x]     = feat[x] - bias - sum_{up pairs} pooled[up_in] @ W[up_k]
//
// Round-1 design: atomic scatters via red.global.add.v4.f32 (4x fewer RED ops
// than scalar atomicAdd), bias+subtract fused into output init + negated
// weights, count-divide fused into the up-side gather, per-warp W[k] column
// cached in registers exploiting k-contiguity of the up map.
// ---------------------------------------------------------------------------

#define C_CH 32

// 128MB static scratch: pooled sums, M <= N = 1e6 rows of 32 fp32.
__device__ float4 g_pooled4[1000000 * 8];

__device__ __forceinline__ void red_add_v4(float* dst, float4 v) {
    asm volatile("red.global.add.v4.f32 [%0], {%1,%2,%3,%4};"
                 :: "l"(dst), "f"(v.x), "f"(v.y), "f"(v.z), "f"(v.w)
                 : "memory");
}

// ---- zero the pooled scratch (only first M rows) ---------------------------
__global__ void zero_pool_kernel(int m8) {
    int t = blockIdx.x * blockDim.x + threadIdx.x;
    if (t < m8) g_pooled4[t] = make_float4(0.f, 0.f, 0.f, 0.f);
}

// ---- out = feat - bias ------------------------------------------------------
__global__ void init_out_kernel(const float4* __restrict__ feat4,
                                const float4* __restrict__ bias4,
                                float4* __restrict__ out4, int n8) {
    int t = blockIdx.x * blockDim.x + threadIdx.x;
    if (t >= n8) return;
    float4 v = feat4[t];
    float4 b = __ldg(bias4 + (t & 7));
    out4[t] = make_float4(v.x - b.x, v.y - b.y, v.z - b.z, v.w - b.w);
}

// ---- pooled[out] += feat[in]  (vectorized: 8 v4-REDs per pair) -------------
__global__ void pool_scatter_kernel(const float4* __restrict__ feat4,
                                    const int* __restrict__ pin,
                                    const int* __restrict__ pout, int p8) {
    int t = blockIdx.x * blockDim.x + threadIdx.x;
    if (t >= p8) return;
    int pair = t >> 3;
    int cg = t & 7;
    int in = __ldg(pin + pair);
    int out = __ldg(pout + pair);
    float4 v = feat4[(size_t)in * 8 + cg];
    red_add_v4((float*)(g_pooled4 + (size_t)out * 8 + cg), v);
}

// ---- out[uout] -= (pooled[uin]/cnt) @ W[uk]  --------------------------------
// One warp handles 32 consecutive pairs. up map is concatenated per offset k,
// so k is constant within a tile except at ~27 boundaries: W[k] column for
// this lane is held (negated) in 32 registers. Pooled rows staged into SMEM
// (float4), inner loop = 8 LDS.128 broadcast + 32 FFMA per pair. Epilogue
// transposes the warp's 32-channel contrib into 8 lanes x float4 and issues
// one v4-RED.
__global__ void __launch_bounds__(256, 4)
up_kernel(const float* __restrict__ weight,
          const int* __restrict__ counts,
          const int* __restrict__ uin,
          const int* __restrict__ uout,
          const int* __restrict__ uk,
          float* __restrict__ out, int U) {
    __shared__ float sh[8][1024];
    int warp = threadIdx.x >> 5;
    int lane = threadIdx.x & 31;
    int base = (blockIdx.x * 8 + warp) * 32;
    if (base >= U) return;
    int tile = min(32, U - base);

    // stage: 4 pairs per iteration, each lane moves one float4 chunk
    int sub = lane >> 3;   // pair-within-group
    int cg = lane & 7;     // float4 chunk within row
    #pragma unroll
    for (int i = 0; i < 8; i++) {
        int j = i * 4 + sub;
        if (j < tile) {
            int in = __ldg(uin + base + j);
            float inv = 1.0f / (float)__ldg(counts + in);
            float4 v = g_pooled4[(size_t)in * 8 + cg];
            *(float4*)&sh[warp][j * 32 + cg * 4] =
                make_float4(v.x * inv, v.y * inv, v.z * inv, v.w * inv);
        }
    }
    __syncwarp();

    float w[32];
    int curk = -1;
    for (int j = 0; j < tile; j++) {
        int p = base + j;
        int k = __ldg(uk + p);
        if (k != curk) {   // warp-uniform; rare (~27 boundaries total)
            curk = k;
            const float* wp = weight + (size_t)k * 1024 + lane;
            #pragma unroll
            for (int c = 0; c < 32; c++) w[c] = -__ldg(wp + c * 32);
        }
        float acc = 0.f;
        const float4* row = (const float4*)&sh[warp][j * 32];
        #pragma unroll
        for (int c4 = 0; c4 < 8; c4++) {
            float4 v = row[c4];
            acc = fmaf(v.x, w[4 * c4 + 0], acc);
            acc = fmaf(v.y, w[4 * c4 + 1], acc);
            acc = fmaf(v.z, w[4 * c4 + 2], acc);
            acc = fmaf(v.w, w[4 * c4 + 3], acc);
        }
        int o = __ldg(uout + p);
        // transpose 32 channels -> 8 lanes x float4, one v4-RED per pair
        float a0 = __shfl_sync(0xffffffffu, acc, (lane & 7) * 4 + 0);
        float a1 = __shfl_sync(0xffffffffu, acc, (lane & 7) * 4 + 1);
        float a2 = __shfl_sync(0xffffffffu, acc, (lane & 7) * 4 + 2);
        float a3 = __shfl_sync(0xffffffffu, acc, (lane & 7) * 4 + 3);
        if (lane < 8)
            red_add_v4(out + (size_t)o * 32 + lane * 4,
                       make_float4(a0, a1, a2, a3));
    }
}

extern "C" void kernel_launch(void* const* d_in, const int* in_sizes, int n_in,
                              void* d_out, int out_size) {
    const float* feat   = (const float*)d_in[0];
    const float* weight = (const float*)d_in[1];
    const float* bias   = (const float*)d_in[2];
    const int* pin      = (const int*)d_in[3];
    const int* pout     = (const int*)d_in[4];
    const int* counts   = (const int*)d_in[5];
    const int* uin      = (const int*)d_in[6];
    const int* uout     = (const int*)d_in[7];
    const int* uk       = (const int*)d_in[8];
    float* out          = (float*)d_out;

    int P = in_sizes[3];
    int M = in_sizes[5];
    int U = in_sizes[6];
    int n8 = out_size / 4;   // N*32 floats -> N*8 float4
    int m8 = M * 8;
    int p8 = P * 8;

    zero_pool_kernel<<<(m8 + 255) / 256, 256>>>(m8);
    init_out_kernel<<<(n8 + 255) / 256, 256>>>(
        (const float4*)feat, (const float4*)bias, (float4*)out, n8);
    pool_scatter_kernel<<<(p8 + 255) / 256, 256>>>(
        (const float4*)feat, pin, pout, p8);
    up_kernel<<<(U + 255) / 256, 256>>>(
        weight, counts, uin, uout, uk, out, U);
}

// round 3
// speedup vs baseline: 1.0246x; 1.0246x over previous
#include <cuda_runtime.h>
#include <cstdint>

// ---------------------------------------------------------------------------
// Round 3:
//   pool: CSR gather (prefix scan + int-atomic fill) — no fp atomics
//   up:   mma.sync tf32 (m16n8k8, split-3 for fp32 precision) over k-sorted
//         64-pair CTA tiles; Bh cached in registers across k-uniform runs;
//         v2-RED scatter epilogue. tcgen05 unavailable at compute_103.
// ---------------------------------------------------------------------------

__device__ float4 g_pooled4[1000000 * 8];   // pooled rows (pre-divided)
__device__ int    g_offsets[1000000];
__device__ int    g_cursor [1000000];
__device__ int    g_bsums  [1024];
__device__ int    g_csr    [12000000];

static __device__ __forceinline__ void red_add_v2(float* dst, float a, float b) {
    asm volatile("red.global.add.v2.f32 [%0], {%1,%2};"
                 :: "l"(dst), "f"(a), "f"(b) : "memory");
}
static __device__ __forceinline__ float trunc_hi(float x) {  // top 10 mantissa bits
    return __uint_as_float(__float_as_uint(x) & 0xFFFFE000u);
}
static __device__ __forceinline__ void mma_tf32(float c[4],
        uint32_t a0, uint32_t a1, uint32_t a2, uint32_t a3,
        uint32_t b0, uint32_t b1) {
    asm volatile(
        "mma.sync.aligned.m16n8k8.row.col.f32.tf32.tf32.f32 "
        "{%0,%1,%2,%3}, {%4,%5,%6,%7}, {%8,%9}, {%0,%1,%2,%3};"
        : "+f"(c[0]), "+f"(c[1]), "+f"(c[2]), "+f"(c[3])
        : "r"(a0), "r"(a1), "r"(a2), "r"(a3), "r"(b0), "r"(b1));
}

// ------------------------------ scan kernels --------------------------------
__global__ void scan1_kernel(const int* __restrict__ counts, int M) {
    __shared__ int sh[32];
    int tid = threadIdx.x, lane = tid & 31, w = tid >> 5;
    int i = blockIdx.x * 1024 + tid;
    int v = (i < M) ? counts[i] : 0;
    int x = v;
    #pragma unroll
    for (int d = 1; d < 32; d <<= 1) { int y = __shfl_up_sync(~0u, x, d); if (lane >= d) x += y; }
    if (lane == 31) sh[w] = x;
    __syncthreads();
    if (w == 0) {
        int s = sh[lane];
        #pragma unroll
        for (int d = 1; d < 32; d <<= 1) { int y = __shfl_up_sync(~0u, s, d); if (lane >= d) s += y; }
        sh[lane] = s;
    }
    __syncthreads();
    int incl = x + (w > 0 ? sh[w - 1] : 0);
    if (i < M) g_offsets[i] = incl - v;
    if (tid == 1023) g_bsums[blockIdx.x] = incl;
}

__global__ void scan2_kernel(int nb) {
    __shared__ int sh[32];
    __shared__ int carry;
    int tid = threadIdx.x, lane = tid & 31, w = tid >> 5;
    if (tid == 0) carry = 0;
    __syncthreads();
    for (int base = 0; base < nb; base += 1024) {
        int i = base + tid;
        int v = (i < nb) ? g_bsums[i] : 0;
        int x = v;
        #pragma unroll
        for (int d = 1; d < 32; d <<= 1) { int y = __shfl_up_sync(~0u, x, d); if (lane >= d) x += y; }
        if (lane == 31) sh[w] = x;
        __syncthreads();
        if (w == 0) {
            int s = sh[lane];
            #pragma unroll
            for (int d = 1; d < 32; d <<= 1) { int y = __shfl_up_sync(~0u, s, d); if (lane >= d) s += y; }
            sh[lane] = s;
        }
        __syncthreads();
        int incl = x + (w > 0 ? sh[w - 1] : 0) + carry;
        if (i < nb) g_bsums[i] = incl - v;
        __syncthreads();
        if (tid == 1023) carry = incl;
        __syncthreads();
    }
}

__global__ void scan3_kernel(int M) {
    int i = blockIdx.x * 256 + threadIdx.x;
    if (i < M) {
        int o = g_offsets[i] + g_bsums[i >> 10];
        g_offsets[i] = o;
        g_cursor[i] = o;
    }
}

__global__ void fill_kernel(const int* __restrict__ pin, const int* __restrict__ pout, int P) {
    int p = blockIdx.x * 256 + threadIdx.x;
    if (p < P) {
        int o = __ldg(pout + p);
        int s = atomicAdd(&g_cursor[o], 1);
        g_csr[s] = __ldg(pin + p);
    }
}

// pooled[m] = (1/count) * sum over CSR row.  8 lanes per pooled row.
__global__ void pool_gather_kernel(const float4* __restrict__ feat4,
                                   const int* __restrict__ counts, int M) {
    int t = blockIdx.x * 256 + threadIdx.x;
    if (t >= M * 8) return;
    int m = t >> 3, cg = t & 7;
    int start = g_offsets[m];
    int cnt = counts[m];
    float4 acc = make_float4(0.f, 0.f, 0.f, 0.f);
    for (int e = 0; e < cnt; e++) {
        int idx = __ldg(&g_csr[start + e]);
        float4 v = __ldg(&feat4[(size_t)idx * 8 + cg]);
        acc.x += v.x; acc.y += v.y; acc.z += v.z; acc.w += v.w;
    }
    float inv = 1.0f / (float)cnt;
    g_pooled4[(size_t)m * 8 + cg] =
        make_float4(acc.x * inv, acc.y * inv, acc.z * inv, acc.w * inv);
}

// ------------------------------- out = feat - bias --------------------------
__global__ void init_out_kernel(const float4* __restrict__ feat4,
                                const float4* __restrict__ bias4,
                                float4* __restrict__ out4, int n8) {
    int t = blockIdx.x * 256 + threadIdx.x;
    if (t >= n8) return;
    float4 v = feat4[t];
    float4 b = __ldg(bias4 + (t & 7));
    out4[t] = make_float4(v.x - b.x, v.y - b.y, v.z - b.z, v.w - b.w);
}

// --------------------- up pass: split-tf32 mma.sync --------------------------
// Tile: CTA = 4 warps x 16 pairs = 64 pairs. D[pair][cout] += A(16x32) x B(32x32)
// A = pooled rows (hi/lo split, SMEM stride 36 floats: conflict-free)
// B = -W[k] (hi regs / lo SMEM, stride 40 floats: conflict-free)
__global__ void __launch_bounds__(128)
up_mma_kernel(const float* __restrict__ weight,
              const int* __restrict__ uin,
              const int* __restrict__ uout,
              const int* __restrict__ uk,
              float* __restrict__ out, int U, int ntiles) {
    __shared__ __align__(16) float sAh[4][16 * 36];
    __shared__ __align__(16) float sAl[4][16 * 36];
    __shared__ __align__(16) float sBh[32 * 40];
    __shared__ __align__(16) float sBl[32 * 40];
    __shared__ int s_in[64], s_out[64], s_k[64];
    __shared__ int s_kmin, s_kmax;

    int tid = threadIdx.x, w = tid >> 5, lane = tid & 31;
    int chunk = (ntiles + gridDim.x - 1) / gridDim.x;
    int t0 = blockIdx.x * chunk;
    int t1 = min(t0 + chunk, ntiles);
    int lastk = -1;
    uint32_t bh[4][4][2];

    int ar = lane >> 2;      // fragment row base
    int ac = lane & 3;       // fragment col base

    for (int t = t0; t < t1; t++) {
        int base = t * 64;
        __syncthreads();     // protect s_* from previous tile's readers
        if (tid == 0) { s_kmin = 1 << 30; s_kmax = -1; }
        if (tid < 64) {
            int p = base + tid;
            int kk = (p < U) ? __ldg(uk + p) : -1;
            s_k[tid] = kk;
            s_in[tid] = (p < U) ? __ldg(uin + p) : 0;
            s_out[tid] = (p < U) ? __ldg(uout + p) : 0;
        }
        __syncthreads();
        if (tid < 64 && s_k[tid] >= 0) {
            atomicMin(&s_kmin, s_k[tid]);
            atomicMax(&s_kmax, s_k[tid]);
        }
        __syncthreads();
        int kmin = s_kmin, kmax = s_kmax;

        float c[4][4];
        #pragma unroll
        for (int i = 0; i < 4; i++)
            #pragma unroll
            for (int j = 0; j < 4; j++) c[i][j] = 0.f;

        for (int k = kmin; k <= kmax; k++) {
            bool newk = (k != lastk);           // uniform across the block
            if (newk) {
                __syncthreads();                // all warps done with old B
                #pragma unroll
                for (int i = 0; i < 8; i++) {
                    int idx = i * 128 + tid;    // 1024 weight elements
                    float v = -__ldg(weight + (size_t)k * 1024 + idx);
                    float vh = trunc_hi(v);
                    int r = idx >> 5, cc = idx & 31;
                    sBh[r * 40 + cc] = vh;
                    sBl[r * 40 + cc] = v - vh;
                }
                __syncthreads();
            }
            // ---- stage A (per-warp, masked to rows whose k matches) ----
            __syncwarp();
            #pragma unroll
            for (int i = 0; i < 4; i++) {
                int idx = i * 32 + lane;        // 128 float4 slots
                int row = idx >> 3, cg = idx & 7;
                bool act = (s_k[w * 16 + row] == k);
                float4 v = act ? __ldg(&g_pooled4[(size_t)s_in[w * 16 + row] * 8 + cg])
                               : make_float4(0.f, 0.f, 0.f, 0.f);
                float4 vh, vl;
                vh.x = trunc_hi(v.x); vl.x = v.x - vh.x;
                vh.y = trunc_hi(v.y); vl.y = v.y - vh.y;
                vh.z = trunc_hi(v.z); vl.z = v.z - vh.z;
                vh.w = trunc_hi(v.w); vl.w = v.w - vh.w;
                *(float4*)&sAh[w][row * 36 + cg * 4] = vh;
                *(float4*)&sAl[w][row * 36 + cg * 4] = vl;
            }
            __syncwarp();
            if (newk) {                          // refill Bh register cache
                #pragma unroll
                for (int nt = 0; nt < 4; nt++)
                    #pragma unroll
                    for (int kt = 0; kt < 4; kt++) {
                        int row = kt * 8 + ac;
                        int col = nt * 8 + ar;
                        bh[nt][kt][0] = __float_as_uint(sBh[row * 40 + col]);
                        bh[nt][kt][1] = __float_as_uint(sBh[(row + 4) * 40 + col]);
                    }
                lastk = k;
            }
            // ---- mma: 3-chain split-tf32 ----
            #pragma unroll
            for (int kt = 0; kt < 4; kt++) {
                int cA = kt * 8 + ac;
                uint32_t ah0 = __float_as_uint(sAh[w][ar * 36 + cA]);
                uint32_t ah1 = __float_as_uint(sAh[w][(ar + 8) * 36 + cA]);
                uint32_t ah2 = __float_as_uint(sAh[w][ar * 36 + cA + 4]);
                uint32_t ah3 = __float_as_uint(sAh[w][(ar + 8) * 36 + cA + 4]);
                uint32_t al0 = __float_as_uint(sAl[w][ar * 36 + cA]);
                uint32_t al1 = __float_as_uint(sAl[w][(ar + 8) * 36 + cA]);
                uint32_t al2 = __float_as_uint(sAl[w][ar * 36 + cA + 4]);
                uint32_t al3 = __float_as_uint(sAl[w][(ar + 8) * 36 + cA + 4]);
                #pragma unroll
                for (int nt = 0; nt < 4; nt++) {
                    int brow = kt * 8 + ac;
                    int bcol = nt * 8 + ar;
                    uint32_t bl0 = __float_as_uint(sBl[brow * 40 + bcol]);
                    uint32_t bl1 = __float_as_uint(sBl[(brow + 4) * 40 + bcol]);
                    mma_tf32(c[nt], ah0, ah1, ah2, ah3, bh[nt][kt][0], bh[nt][kt][1]);
                    mma_tf32(c[nt], ah0, ah1, ah2, ah3, bl0, bl1);
                    mma_tf32(c[nt], al0, al1, al2, al3, bh[nt][kt][0], bh[nt][kt][1]);
                }
            }
        }
        // ---- epilogue: RED-scatter (each lane: 2 rows x 4 v2-REDs) ----
        int p0 = base + w * 16 + ar;
        int p1 = p0 + 8;
        int o0 = s_out[w * 16 + ar];
        int o1 = s_out[w * 16 + ar + 8];
        float* d0 = out + (size_t)o0 * 32 + ac * 2;
        float* d1 = out + (size_t)o1 * 32 + ac * 2;
        #pragma unroll
        for (int nt = 0; nt < 4; nt++) {
            if (p0 < U) red_add_v2(d0 + nt * 8, c[nt][0], c[nt][1]);
            if (p1 < U) red_add_v2(d1 + nt * 8, c[nt][2], c[nt][3]);
        }
    }
}

// ------------------------------------ launch --------------------------------
extern "C" void kernel_launch(void* const* d_in, const int* in_sizes, int n_in,
                              void* d_out, int out_size) {
    const float* feat   = (const float*)d_in[0];
    const float* weight = (const float*)d_in[1];
    const float* bias   = (const float*)d_in[2];
    const int* pin      = (const int*)d_in[3];
    const int* pout     = (const int*)d_in[4];
    const int* counts   = (const int*)d_in[5];
    const int* uin      = (const int*)d_in[6];
    const int* uout     = (const int*)d_in[7];
    const int* uk       = (const int*)d_in[8];
    float* out          = (float*)d_out;

    int P = in_sizes[3];
    int M = in_sizes[5];
    int U = in_sizes[6];
    int n8 = out_size / 4;

    int nb = (M + 1023) / 1024;
    scan1_kernel<<<nb, 1024>>>(counts, M);
    scan2_kernel<<<1, 1024>>>(nb);
    scan3_kernel<<<(M + 255) / 256, 256>>>(M);
    fill_kernel<<<(P + 255) / 256, 256>>>(pin, pout, P);
    pool_gather_kernel<<<(M * 8 + 255) / 256, 256>>>((const float4*)feat, counts, M);
    init_out_kernel<<<(n8 + 255) / 256, 256>>>(
        (const float4*)feat, (const float4*)bias, (float4*)out, n8);

    int ntiles = (U + 63) / 64;
    int grid = ntiles < 1024 ? ntiles : 1024;
    up_mma_kernel<<<grid, 128>>>(weight, uin, uout, uk, out, U, ntiles);
}